// round 3
// baseline (speedup 1.0000x reference)
#include <cuda_runtime.h>
#include <math.h>

#define FULLMASK 0xffffffffu

// Inverse (source-index) maps for composed CNOT relabels on the 6 register bits
// (wires 4..9). Even gates (4,5)(6,7)(8,9):
#define ASRC(d) ( ((d)&1) \
    | (((((d)>>1)^(d))&1)<<1) \
    | ((((d)>>2)&1)<<2) \
    | (((((d)>>3)^((d)>>2))&1)<<3) \
    | ((((d)>>4)&1)<<4) \
    | (((((d)>>5)^((d)>>4))&1)<<5) )
// Odd gates (5,6)(7,8):
#define BSRC(d) ( ((d)&1) \
    | ((((d)>>1)&1)<<1) \
    | (((((d)>>2)^((d)>>1))&1)<<2) \
    | ((((d)>>3)&1)<<3) \
    | (((((d)>>4)^((d)>>3))&1)<<4) \
    | ((((d)>>5)&1)<<5) )

__device__ __forceinline__ float fast_tanh(float x) {
    float e;
    asm("ex2.approx.f32 %0, %1;" : "=f"(e) : "f"(x * 2.88539008177792681f));
    return (e - 1.0f) * __frcp_rn(e + 1.0f);
}

__global__ __launch_bounds__(256, 1)
void dq_kernel(const float* __restrict__ x,
               const float* __restrict__ W1,
               const float* __restrict__ b1,
               const float* __restrict__ qw,
               const float* __restrict__ W2,
               const float* __restrict__ b2,
               float* __restrict__ out)
{
    __shared__ alignas(16) float sW1[10][512];   // W1 transposed: [q][d]
    __shared__ float sW2[640];       // [10][64]
    __shared__ float sb2[64];
    __shared__ float sb1[10];
    __shared__ float sqt[6][10];     // tan(theta/2)
    __shared__ float sC[6];          // prod of 10 cos(theta/2) per layer
    __shared__ float scc[64];

    const int tid = threadIdx.x;

    // ---- stage weights ----
#pragma unroll 4
    for (int i = tid; i < 5120; i += 256) {
        int d = i / 10, q = i - d * 10;
        sW1[q][d] = W1[i];
    }
    for (int i = tid; i < 640; i += 256) sW2[i] = W2[i];
    if (tid < 64) sb2[tid] = b2[tid];
    if (tid < 10) sb1[tid] = b1[tid];
    if (tid < 60) {
        float th = 0.5f * qw[tid];
        float s = __sinf(th), c = __cosf(th);
        sqt[tid / 10][tid % 10] = s * __frcp_rn(c);
        scc[tid] = c;
    }
    __syncthreads();
    if (tid < 6) {
        float p = 1.f;
#pragma unroll
        for (int w = 0; w < 10; w++) p *= scc[tid * 10 + w];
        sC[tid] = p;
    }
    __syncthreads();

    const int warp = tid >> 5;
    const int lane = tid & 31;
    const int s    = lane >> 4;          // sample within warp (0/1)
    const int l    = lane & 15;          // 4 lane wire bits
    const int sbase = s << 4;
    const int sample = blockIdx.x * 16 + warp * 2 + s;
    const float* xr = x + (size_t)sample * 512;

    // Composed lane-CNOT source lane (wires 0-3): even (0,1)(2,3) then odd (1,2)
    // inverse: (l0, l1^l0, l2^l1, l3^l2^l1)
    const int lsrc = sbase | (l & 1)
        | ((((l >> 1) ^ l) & 1) << 1)
        | ((((l >> 2) ^ (l >> 1)) & 1) << 2)
        | ((((l >> 3) ^ (l >> 2) ^ (l >> 1)) & 1) << 3);
    // Mixed CNOT(3,4): ctrl = lane bit 3 (logical frame, applied after lane perm)
    const bool qsw = (l >> 3) & 1;
    float sgn[4];
#pragma unroll
    for (int w = 0; w < 4; w++) sgn[w] = ((l >> w) & 1) ? 1.f : -1.f;

    // ---- angles = tanh(x@W1 + b1) * pi/2; per-wire u/v ----
    const float4* x4 = (const float4*)xr;
    float4 xv[8];
#pragma unroll
    for (int t = 0; t < 8; t++) xv[t] = x4[l + 16 * t];

    float u[10], v[10];
#pragma unroll
    for (int q = 0; q < 10; q++) {
        const float4* w4 = (const float4*)(&sW1[q][0]);
        float p = 0.f;
#pragma unroll
        for (int t = 0; t < 8; t++) {
            float4 wv = w4[l + 16 * t];
            p = fmaf(xv[t].x, wv.x, p);
            p = fmaf(xv[t].y, wv.y, p);
            p = fmaf(xv[t].z, wv.z, p);
            p = fmaf(xv[t].w, wv.w, p);
        }
#pragma unroll
        for (int off = 8; off; off >>= 1) p += __shfl_xor_sync(FULLMASK, p, off);
        float ang = fast_tanh(p + sb1[q]) * 1.57079632679489662f;
        float hh = 0.5f * ang;
        float sn = __sinf(hh), cs = __cosf(hh);
        u[q] = (cs - sn) * 0.70710678118654752f;
        v[q] = (cs + sn) * 0.70710678118654752f;
    }

    // ---- build product state: 4 lane wires (0-3), 6 reg wires (4-9) ----
    float st[64];
    float L = 1.f;
#pragma unroll
    for (int w = 0; w < 4; w++) L *= ((l >> w) & 1) ? v[w] : u[w];
    st[0] = L;
#pragma unroll
    for (int b = 0; b < 6; b++) {
        const int m = 1 << b;
        const int w = 4 + b;
#pragma unroll
        for (int r = 0; r < 64; r++) {
            if (r < m) {
                st[r + m] = st[r] * v[w];
                st[r]     = st[r] * u[w];
            }
        }
    }

    // ---- 6 layers ----
#pragma unroll
    for (int k = 0; k < 6; k++) {
        // (1) composed lane CNOTs (0,1)(2,3)(1,2): one shuffle pass
#pragma unroll
        for (int r = 0; r < 64; r++)
            st[r] = __shfl_sync(FULLMASK, st[r], lsrc);
        // (2) even reg CNOTs (4,5)(6,7)(8,9): free relabel
        {
            float tp[64];
#pragma unroll
            for (int r = 0; r < 64; r++) tp[r] = st[ASRC(r)];
#pragma unroll
            for (int r = 0; r < 64; r++) st[r] = tp[r];
        }
        // (3) mixed CNOT(3,4): lane-bit-3 ctrl, reg-bit-0 tgt
#pragma unroll
        for (int i = 0; i < 32; i++) {
            float a = st[2 * i], b = st[2 * i + 1];
            st[2 * i]     = qsw ? b : a;
            st[2 * i + 1] = qsw ? a : b;
        }
        // (4) odd reg CNOTs (5,6)(7,8): free relabel
        {
            float tp[64];
#pragma unroll
            for (int r = 0; r < 64; r++) tp[r] = st[BSRC(r)];
#pragma unroll
            for (int r = 0; r < 64; r++) st[r] = tp[r];
        }
        // (5) RY on lane wires 0-3, cosine deferred
#pragma unroll
        for (int w = 0; w < 4; w++) {
            float tq = sgn[w] * sqt[k][w];
            const int m = 1 << w;
#pragma unroll
            for (int r = 0; r < 64; r++) {
                float o = __shfl_xor_sync(FULLMASK, st[r], m);
                st[r] = fmaf(tq, o, st[r]);
            }
        }
        // (6) RY on reg wires 4-9, cosine deferred
#pragma unroll
        for (int b = 0; b < 6; b++) {
            float tw = sqt[k][4 + b];
            const int m = 1 << b;
#pragma unroll
            for (int r = 0; r < 64; r++) {
                if ((r & m) == 0) {
                    float a0 = st[r], a1 = st[r + m];
                    st[r]     = fmaf(-tw, a1, a0);
                    st[r + m] = fmaf( tw, a0, a1);
                }
            }
        }
        // (7) apply all 10 deferred cosines
        {
            float Ck = sC[k];
#pragma unroll
            for (int r = 0; r < 64; r++) st[r] *= Ck;
        }
    }

    // ---- measurement ----
    float T = 0.f;
#pragma unroll
    for (int r = 0; r < 64; r++) {
        st[r] = st[r] * st[r];
        T += st[r];
    }

    float e[10];
    // lane wires 0-3: shared Walsh tree within 16-lane half
    {
        float sacc = T;
#pragma unroll
        for (int w = 0; w < 4; w++) {
            const int m = 1 << w;
            float o = __shfl_xor_sync(FULLMASK, sacc, m);
            float d = ((l >> w) & 1) ? (o - sacc) : (sacc - o);
            sacc = sacc + o;
#pragma unroll
            for (int mm = 2 * m; mm < 16; mm <<= 1)
                d += __shfl_xor_sync(FULLMASK, d, mm);
            e[w] = d;
        }
    }
    // reg wires 4-9: pair-tree over 64 regs, then 16-lane all-reduce
    {
        float p0[32], p1[16], p2[8], p3[4], p4[2];
        float d0 = 0.f, d1 = 0.f, d2 = 0.f, d3 = 0.f, d4 = 0.f, d5;
#pragma unroll
        for (int i = 0; i < 32; i++) { p0[i] = st[2*i] + st[2*i+1]; d0 += st[2*i] - st[2*i+1]; }
#pragma unroll
        for (int i = 0; i < 16; i++) { p1[i] = p0[2*i] + p0[2*i+1]; d1 += p0[2*i] - p0[2*i+1]; }
#pragma unroll
        for (int i = 0; i < 8; i++)  { p2[i] = p1[2*i] + p1[2*i+1]; d2 += p1[2*i] - p1[2*i+1]; }
#pragma unroll
        for (int i = 0; i < 4; i++)  { p3[i] = p2[2*i] + p2[2*i+1]; d3 += p2[2*i] - p2[2*i+1]; }
#pragma unroll
        for (int i = 0; i < 2; i++)  { p4[i] = p3[2*i] + p3[2*i+1]; d4 += p3[2*i] - p3[2*i+1]; }
        d5 = p4[0] - p4[1];
        float dd[6] = {d0, d1, d2, d3, d4, d5};
#pragma unroll
        for (int b = 0; b < 6; b++) {
            float acc = dd[b];
#pragma unroll
            for (int off = 8; off; off >>= 1) acc += __shfl_xor_sync(FULLMASK, acc, off);
            e[4 + b] = acc;
        }
    }

    // ---- out = e @ W2 + b2 ----
#pragma unroll
    for (int t = 0; t < 4; t++) {
        int o = l + 16 * t;
        float acc = sb2[o];
#pragma unroll
        for (int q = 0; q < 10; q++) acc = fmaf(e[q], sW2[q * 64 + o], acc);
        out[(size_t)sample * 64 + o] = acc;
    }
}

extern "C" void kernel_launch(void* const* d_in, const int* in_sizes, int n_in,
                              void* d_out, int out_size) {
    const float* x  = (const float*)d_in[0];
    const float* W1 = (const float*)d_in[1];
    const float* b1 = (const float*)d_in[2];
    const float* qw = (const float*)d_in[3];
    const float* W2 = (const float*)d_in[4];
    const float* b2 = (const float*)d_in[5];
    float* out = (float*)d_out;

    int B = in_sizes[0] / 512;          // 8192
    int grid = B / 16;                  // 16 samples per 256-thread block (2/warp)
    dq_kernel<<<grid, 256>>>(x, W1, b1, qw, W2, b2, out);
}